// round 16
// baseline (speedup 1.0000x reference)
#include <cuda_runtime.h>
#include <cuda_fp16.h>

#define B_    16
#define CIN   512
#define NPIX  4096
#define CC    64
#define NSPLIT 32

// Scratch (static device globals; no allocation)
__device__ float g_qkv[(size_t)B_ * 3 * CC * NPIX];          // [b][{q,k,v}][64][4096]
__device__ float g_Spart[(size_t)B_ * NSPLIT * CC * CC];     // split-K partials of S
__device__ float g_attn[(size_t)B_ * CC * CC];               // softmax(S) per batch
__device__ float g_W2[(size_t)B_ * CIN * CC];                // gamma * (Wo @ attn) per batch

// ---------------------------------------------------------------------------
// fp16 3-term split helpers (a = hi + lo, both fp16; products accum in fp32)
// ---------------------------------------------------------------------------
__device__ __forceinline__ void split2(float x, float y, unsigned& hu, unsigned& lu) {
    __half hx = __float2half_rn(x), hy = __float2half_rn(y);
    __half2 H = __halves2half2(hx, hy);
    __half2 L = __floats2half2_rn(x - __half2float(hx), y - __half2float(hy));
    hu = reinterpret_cast<unsigned&>(H);
    lu = reinterpret_cast<unsigned&>(L);
}

__device__ __forceinline__ unsigned cvt_hi2(float x, float y) {
    __half2 H = __floats2half2_rn(x, y);
    return reinterpret_cast<unsigned&>(H);
}

__device__ __forceinline__ void mma_f16(float* d, const unsigned* a, const unsigned* b) {
    asm volatile(
        "mma.sync.aligned.m16n8k16.row.col.f32.f16.f16.f32 "
        "{%0,%1,%2,%3}, {%4,%5,%6,%7}, {%8,%9}, {%0,%1,%2,%3};"
        : "+f"(d[0]), "+f"(d[1]), "+f"(d[2]), "+f"(d[3])
        : "r"(a[0]), "r"(a[1]), "r"(a[2]), "r"(a[3]), "r"(b[0]), "r"(b[1]));
}

__device__ __forceinline__ void ldsm_x4(unsigned* r, unsigned addr) {
    asm volatile("ldmatrix.sync.aligned.m8n8.x4.shared.b16 {%0,%1,%2,%3}, [%4];"
                 : "=r"(r[0]), "=r"(r[1]), "=r"(r[2]), "=r"(r[3]) : "r"(addr));
}

__device__ __forceinline__ unsigned sptr(const void* p) {
    return (unsigned)__cvta_generic_to_shared(p);
}

#define PA  12   // A row stride in words (16B-aligned rows for ldmatrix)
#define PBQ 72   // B row stride, N=64 tile
#define PBO 136  // B row stride, N=128 tile

// ---------------------------------------------------------------------------
// Kernel 1: FUSED QKV projection (x read once), fp16 MMA, double buffer.
// M=192 (rows 0-63 Q, 64-127 K, 128-191 V), N-tile=64, K=512.
// SMSP-balanced tile mapping; V tiles 2-term, Q/K 3-term.
// grid (64 n-tiles, 16 batches), 256 threads
// ---------------------------------------------------------------------------
union SmemQKV {
    struct {
        unsigned Ah[2][192][PA], Al[2][192][PA];   // 36864 B
        unsigned Bh[2][8][PBQ],  Bl[2][8][PBQ];    //  9216 B
    } ab;                       // 46080 B
    float stage[96][68];        // 26112 B (two-pass epilogue staging)
};

__global__ __launch_bounds__(256, 2) void qkv_mma_kernel(
    const float* __restrict__ x,
    const float* __restrict__ Wq, const float* __restrict__ bq,
    const float* __restrict__ Wk, const float* __restrict__ bk,
    const float* __restrict__ Wv, const float* __restrict__ bv)
{
    const int n0 = blockIdx.x * 64;
    const int b  = blockIdx.y;
    const float* xb = x + (size_t)b * CIN * NPIX;
    float* out = g_qkv + (size_t)b * 3 * CC * NPIX;

    __shared__ SmemQKV su;

    const int tid  = threadIdx.x;
    const int warp = tid >> 5;
    const int lane = tid & 31;
    const int wm = warp & 3;          // 0..3 -> 16-row sub-slab within each of Q/K/V
    const int wn = warp >> 2;         // 0..1 -> 32-col slab
    const int g  = lane >> 2;
    const int t  = lane & 3;

    const int lrow = lane & 15;
    const int lwB  = (lane >> 4) * 16;

    const int arow = tid >> 2;           // 0..63
    const int ak4  = (tid & 3) * 4;      // 0,4,8,12
    const bool bact = (tid < 128);
    const int jb   = tid >> 4;           // 0..7 for tid<128
    const int c4   = (tid & 15) * 4;     // 0..60

    float acc[3][4][4];
    #pragma unroll
    for (int mt = 0; mt < 3; mt++)
        #pragma unroll
        for (int nt = 0; nt < 4; nt++)
            #pragma unroll
            for (int i = 0; i < 4; i++) acc[mt][nt][i] = 0.f;

    const int NT = CIN / 16;  // 32
    float4 aP[3], bP0, bP1;

    {
        aP[0] = *(const float4*)&Wq[(size_t)arow * CIN + ak4];
        aP[1] = *(const float4*)&Wk[(size_t)arow * CIN + ak4];
        aP[2] = *(const float4*)&Wv[(size_t)arow * CIN + ak4];
        if (bact) {
            bP0 = *(const float4*)&xb[(size_t)(2 * jb) * NPIX + n0 + c4];
            bP1 = *(const float4*)&xb[(size_t)(2 * jb + 1) * NPIX + n0 + c4];
        }
    }

    for (int it = 0; it < NT; it++) {
        const int s = it & 1;
        #pragma unroll
        for (int r = 0; r < 3; r++) {
            unsigned h0, l0, h1, l1;
            split2(aP[r].x, aP[r].y, h0, l0);
            split2(aP[r].z, aP[r].w, h1, l1);
            *(uint2*)&su.ab.Ah[s][r * 64 + arow][ak4 >> 1] = make_uint2(h0, h1);
            *(uint2*)&su.ab.Al[s][r * 64 + arow][ak4 >> 1] = make_uint2(l0, l1);
        }
        if (bact) {
            unsigned bh4[4], bl4[4];
            split2(bP0.x, bP1.x, bh4[0], bl4[0]);
            split2(bP0.y, bP1.y, bh4[1], bl4[1]);
            split2(bP0.z, bP1.z, bh4[2], bl4[2]);
            split2(bP0.w, bP1.w, bh4[3], bl4[3]);
            *(uint4*)&su.ab.Bh[s][jb][c4] = make_uint4(bh4[0], bh4[1], bh4[2], bh4[3]);
            *(uint4*)&su.ab.Bl[s][jb][c4] = make_uint4(bl4[0], bl4[1], bl4[2], bl4[3]);
        }
        __syncthreads();

        if (it + 1 < NT) {
            const int kk = (it + 1) * 16;
            aP[0] = *(const float4*)&Wq[(size_t)arow * CIN + kk + ak4];
            aP[1] = *(const float4*)&Wk[(size_t)arow * CIN + kk + ak4];
            aP[2] = *(const float4*)&Wv[(size_t)arow * CIN + kk + ak4];
            if (bact) {
                bP0 = *(const float4*)&xb[(size_t)(kk + 2 * jb) * NPIX + n0 + c4];
                bP1 = *(const float4*)&xb[(size_t)(kk + 2 * jb + 1) * NPIX + n0 + c4];
            }
        }

        unsigned ah[3][4], al[3][4], bh[4][2], bl[4][2];
        const unsigned baseAh = sptr(&su.ab.Ah[s][0][0]);
        const unsigned baseAl = sptr(&su.ab.Al[s][0][0]);
        #pragma unroll
        for (int mt = 0; mt < 3; mt++) {
            int rb = mt * 64 + wm * 16;          // one Q, one K, one V tile per warp
            unsigned roff = (unsigned)(rb + lrow) * (PA * 4) + lwB;
            ldsm_x4(ah[mt], baseAh + roff);
            ldsm_x4(al[mt], baseAl + roff);
        }
        #pragma unroll
        for (int nt = 0; nt < 4; nt++) {
            int nb = wn * 32 + nt * 8;
            bh[nt][0] = su.ab.Bh[s][t    ][nb + g];
            bh[nt][1] = su.ab.Bh[s][t + 4][nb + g];
            bl[nt][0] = su.ab.Bl[s][t    ][nb + g];
            bl[nt][1] = su.ab.Bl[s][t + 4][nb + g];
        }
        #pragma unroll
        for (int mt = 0; mt < 3; mt++) {
            #pragma unroll
            for (int nt = 0; nt < 4; nt++) {
                mma_f16(acc[mt][nt], al[mt], bh[nt]);
                if (mt != 2) mma_f16(acc[mt][nt], ah[mt], bl[nt]);   // V (mt==2): 2-term
                mma_f16(acc[mt][nt], ah[mt], bh[nt]);
            }
        }
    }
    __syncthreads();   // protect union reuse (stage aliases ab)

    // two-pass staged epilogue: rows [0,96) then [96,192)
    #pragma unroll
    for (int pass = 0; pass < 2; pass++) {
        #pragma unroll
        for (int mt = 0; mt < 3; mt++) {
            int grow0 = mt * 64 + wm * 16;
            if (grow0 >= pass * 96 && grow0 < pass * 96 + 96) {
                int r0 = grow0 - pass * 96 + g;
                #pragma unroll
                for (int nt = 0; nt < 4; nt++) {
                    int c = wn * 32 + nt * 8 + 2 * t;
                    su.stage[r0][c]         = acc[mt][nt][0];
                    su.stage[r0][c + 1]     = acc[mt][nt][1];
                    su.stage[r0 + 8][c]     = acc[mt][nt][2];
                    su.stage[r0 + 8][c + 1] = acc[mt][nt][3];
                }
            }
        }
        __syncthreads();
        #pragma unroll
        for (int i = 0; i < 6; i++) {
            int e   = tid + i * 256;
            int row = e >> 4;
            int cc4 = (e & 15) * 4;
            int grow = pass * 96 + row;
            int jj  = grow >> 6;
            const float* bp = (jj == 0) ? bq : (jj == 1) ? bk : bv;
            float bb = bp[grow & 63];
            float4 v = *(const float4*)&su.stage[row][cc4];
            v.x += bb; v.y += bb; v.z += bb; v.w += bb;
            *(float4*)&out[(size_t)grow * NPIX + n0 + cc4] = v;
        }
        __syncthreads();
    }
}

// ---------------------------------------------------------------------------
// Kernel 2: split-K partials of S[b] = Q[64,4096] @ K_view[4096,64]  (fp32)
// ---------------------------------------------------------------------------
__global__ __launch_bounds__(256) void s_kernel()
{
    const int s = blockIdx.x;
    const int b = blockIdx.y;
    const float* Q  = g_qkv + (size_t)(b * 3 + 0) * CC * NPIX;
    const float* Kp = g_qkv + (size_t)(b * 3 + 1) * CC * NPIX;  // flat reshape view

    __shared__ float Qs[64][17];
    __shared__ float Ks[16][64];

    const int tid = threadIdx.x;
    const int tx = tid & 15, ty = tid >> 4;
    const int nbase = s * (NPIX / NSPLIT);   // 128 n per split

    float acc[4][4];
    #pragma unroll
    for (int i = 0; i < 4; i++)
        #pragma unroll
        for (int jj = 0; jj < 4; jj++) acc[i][jj] = 0.f;

    for (int kk = 0; kk < NPIX / NSPLIT; kk += 16) {
        #pragma unroll
        for (int e = tid; e < 1024; e += 256) {
            int i = e >> 4, k = e & 15;
            Qs[i][k] = Q[(size_t)i * NPIX + nbase + kk + k];
        }
        #pragma unroll
        for (int e = tid; e < 1024; e += 256) {
            int k = e >> 6, d = e & 63;
            Ks[k][d] = Kp[(size_t)(nbase + kk + k) * CC + d];
        }
        __syncthreads();
        #pragma unroll
        for (int k = 0; k < 16; k++) {
            float av[4];
            #pragma unroll
            for (int i = 0; i < 4; i++) av[i] = Qs[ty * 4 + i][k];
            float4 bv4 = *(const float4*)&Ks[k][tx * 4];
            float bv_[4] = {bv4.x, bv4.y, bv4.z, bv4.w};
            #pragma unroll
            for (int i = 0; i < 4; i++)
                #pragma unroll
                for (int jj = 0; jj < 4; jj++) acc[i][jj] += av[i] * bv_[jj];
        }
        __syncthreads();
    }
    float* part = g_Spart + ((size_t)b * NSPLIT + s) * CC * CC;
    #pragma unroll
    for (int i = 0; i < 4; i++)
        #pragma unroll
        for (int jj = 0; jj < 4; jj++)
            part[(ty * 4 + i) * CC + tx * 4 + jj] = acc[i][jj];
}

// ---------------------------------------------------------------------------
// Kernel 3a: reduce partials -> S, row softmax -> attn (global).
// grid (16 batches), 512 threads
// ---------------------------------------------------------------------------
__global__ __launch_bounds__(512) void softmax_kernel()
{
    const int b = blockIdx.x;
    const int tid = threadIdx.x;
    __shared__ float sA[CC * CC];

    for (int e = tid; e < CC * CC; e += 512) {
        const float* p = g_Spart + (size_t)b * NSPLIT * CC * CC + e;
        float v = 0.f;
        #pragma unroll
        for (int s = 0; s < NSPLIT; s++) v += p[(size_t)s * CC * CC];
        sA[e] = v;
    }
    __syncthreads();

    if (tid < CC) {
        float* row = &sA[tid * CC];
        float mx = row[0];
        #pragma unroll
        for (int d = 1; d < CC; d++) mx = fmaxf(mx, row[d]);
        float sum = 0.f;
        #pragma unroll
        for (int d = 0; d < CC; d++) { float e = __expf(row[d] - mx); row[d] = e; sum += e; }
        float inv = 1.f / sum;
        #pragma unroll
        for (int d = 0; d < CC; d++) row[d] *= inv;
    }
    __syncthreads();

    float* ab = g_attn + (size_t)b * CC * CC;
    for (int e = tid; e < CC * CC; e += 512)
        ab[e] = sA[e];
}

// ---------------------------------------------------------------------------
// Kernel 3b: W2[b] = gamma * Wo @ attn[b].  [512,64]@[64,64] per batch.
// grid (32 m-tiles of 16 rows, 16 batches) = 512 blocks, 256 threads;
// 4 outputs per thread.
// ---------------------------------------------------------------------------
__global__ __launch_bounds__(256) void w2_kernel(
    const float* __restrict__ Wo, const float* __restrict__ gamma)
{
    const int m0 = blockIdx.x * 16;
    const int b  = blockIdx.y;
    const int tid = threadIdx.x;

    __shared__ float aW[CC][CC + 4];   // attn, padded
    __shared__ float wo[16][CC + 4];   // Wo rows m0..m0+15

    #pragma unroll
    for (int i = 0; i < 4; i++) {
        int e = tid + i * 256;
        int r = e >> 4, c4 = (e & 15) * 4;
        float4 va = *(const float4*)&g_attn[(size_t)b * CC * CC + r * CC + c4];
        *(float4*)&aW[r][c4] = va;
    }
    {
        int r = tid >> 4, c4 = (tid & 15) * 4;
        float4 vw = *(const float4*)&Wo[(size_t)(m0 + r) * CC + c4];
        *(float4*)&wo[r][c4] = vw;
    }
    __syncthreads();

    const int ol = tid >> 4;           // 0..15 local output row
    const int cs = (tid & 15) * 4;     // 4-col segment

    float acc[4] = {0.f, 0.f, 0.f, 0.f};

    #pragma unroll
    for (int e = 0; e < CC; e++) {
        float w = wo[ol][e];
        float4 v = *(const float4*)&aW[e][cs];
        acc[0] += w * v.x;
        acc[1] += w * v.y;
        acc[2] += w * v.z;
        acc[3] += w * v.w;
    }

    const float g = gamma[0];
    float* w2 = g_W2 + ((size_t)b * CIN + m0 + ol) * CC + cs;
    float4 v = make_float4(g * acc[0], g * acc[1], g * acc[2], g * acc[3]);
    *(float4*)w2 = v;
}

// ---------------------------------------------------------------------------
// Kernel 4: out = W2[b][512,64] @ V[b][64,4096] + gamma*bo + x.
// 2-term fp16 MMA: W2 split hi/lo, V hi only.
// GRID REORDER: m-tile is the FASTEST dimension so the 8 blocks sharing a
// V slice are scheduled adjacently -> V re-reads hit L2 (saves ~130MB DRAM).
// grid (8 m-tiles, 32 n-tiles, 16 batches), 256 threads (8 warps, 2x4)
// ---------------------------------------------------------------------------
union SmemOut {
    struct {
        unsigned Ah[2][64][PA], Al[2][64][PA];    // 12288 B
        unsigned Bh[2][8][PBO];                   //  8704 B
    } ab;                       // 20992 B
    float stage[64][132];       // 33792 B
};

__global__ __launch_bounds__(256, 3) void out_mma_kernel(
    const float* __restrict__ x, const float* __restrict__ bo,
    const float* __restrict__ gamma, float* __restrict__ out)
{
    const int m0 = blockIdx.x * 64;      // FAST: m-tile
    const int n0 = blockIdx.y * 128;     // SLOW: n-tile
    const int b  = blockIdx.z;
    const float* W  = g_W2 + (size_t)b * CIN * CC;
    const float* V  = g_qkv + (size_t)(b * 3 + 2) * CC * NPIX;
    const float* xb = x + (size_t)b * CIN * NPIX;
    float* ob = out + (size_t)b * CIN * NPIX;

    __shared__ SmemOut su;

    const int tid  = threadIdx.x;
    const int warp = tid >> 5;
    const int lane = tid & 31;
    const int wm = warp & 1;
    const int wn = warp >> 1;
    const int g  = lane >> 2;
    const int t  = lane & 3;

    const int lrow = lane & 15;
    const int lwB  = (lane >> 4) * 16;

    const int m_st = tid >> 2;
    const int k4   = (tid & 3) * 4;
    const int jb   = tid >> 5;
    const int n4b  = (tid & 31) * 4;

    float acc[2][4][4];
    #pragma unroll
    for (int mt = 0; mt < 2; mt++)
        #pragma unroll
        for (int nt = 0; nt < 4; nt++)
            #pragma unroll
            for (int i = 0; i < 4; i++) acc[mt][nt][i] = 0.f;

    const int NT = CC / 16;  // 4
    float4 aP, bP0, bP1;

    aP  = *(const float4*)&W[(size_t)(m0 + m_st) * CC + k4];
    bP0 = *(const float4*)&V[(size_t)(2 * jb) * NPIX + n0 + n4b];
    bP1 = *(const float4*)&V[(size_t)(2 * jb + 1) * NPIX + n0 + n4b];

    #pragma unroll
    for (int it = 0; it < NT; it++) {
        const int s = it & 1;
        {
            unsigned h0, l0, h1, l1;
            split2(aP.x, aP.y, h0, l0);
            split2(aP.z, aP.w, h1, l1);
            *(uint2*)&su.ab.Ah[s][m_st][k4 >> 1] = make_uint2(h0, h1);
            *(uint2*)&su.ab.Al[s][m_st][k4 >> 1] = make_uint2(l0, l1);
            unsigned bh4[4];
            bh4[0] = cvt_hi2(bP0.x, bP1.x);
            bh4[1] = cvt_hi2(bP0.y, bP1.y);
            bh4[2] = cvt_hi2(bP0.z, bP1.z);
            bh4[3] = cvt_hi2(bP0.w, bP1.w);
            *(uint4*)&su.ab.Bh[s][jb][n4b] = make_uint4(bh4[0], bh4[1], bh4[2], bh4[3]);
        }
        __syncthreads();

        if (it + 1 < NT) {
            const int kk = (it + 1) * 16;
            aP  = *(const float4*)&W[(size_t)(m0 + m_st) * CC + kk + k4];
            bP0 = *(const float4*)&V[(size_t)(kk + 2 * jb) * NPIX + n0 + n4b];
            bP1 = *(const float4*)&V[(size_t)(kk + 2 * jb + 1) * NPIX + n0 + n4b];
        }

        unsigned ah[2][4], al[2][4], bh[4][2];
        const unsigned baseAh = sptr(&su.ab.Ah[s][0][0]);
        const unsigned baseAl = sptr(&su.ab.Al[s][0][0]);
        #pragma unroll
        for (int mt = 0; mt < 2; mt++) {
            int rb = wm * 32 + mt * 16;
            unsigned roff = (unsigned)(rb + lrow) * (PA * 4) + lwB;
            ldsm_x4(ah[mt], baseAh + roff);
            ldsm_x4(al[mt], baseAl + roff);
        }
        #pragma unroll
        for (int nt = 0; nt < 4; nt++) {
            int nb = wn * 32 + nt * 8;
            bh[nt][0] = su.ab.Bh[s][t    ][nb + g];
            bh[nt][1] = su.ab.Bh[s][t + 4][nb + g];
        }
        #pragma unroll
        for (int mt = 0; mt < 2; mt++)
            #pragma unroll
            for (int nt = 0; nt < 4; nt++)
                mma_f16(acc[mt][nt], al[mt], bh[nt]);
        #pragma unroll
        for (int mt = 0; mt < 2; mt++)
            #pragma unroll
            for (int nt = 0; nt < 4; nt++)
                mma_f16(acc[mt][nt], ah[mt], bh[nt]);
        // no trailing barrier (double-buffered)
    }
    __syncthreads();   // protect union reuse

    // stage accumulators into smem
    #pragma unroll
    for (int mt = 0; mt < 2; mt++) {
        int r0 = wm * 32 + mt * 16 + g;
        #pragma unroll
        for (int nt = 0; nt < 4; nt++) {
            int c = wn * 32 + nt * 8 + 2 * t;
            su.stage[r0][c]         = acc[mt][nt][0];
            su.stage[r0][c + 1]     = acc[mt][nt][1];
            su.stage[r0 + 8][c]     = acc[mt][nt][2];
            su.stage[r0 + 8][c + 1] = acc[mt][nt][3];
        }
    }
    __syncthreads();

    // coalesced stream: out = stage + gamma*bo + x   (64x128 = 2048 float4)
    const float gm = gamma[0];
    #pragma unroll
    for (int i = 0; i < 8; i++) {
        int e   = tid + i * 256;
        int row = e >> 5;
        int cc4 = (e & 31) * 4;
        int rg  = m0 + row;
        float bb = gm * bo[rg];
        float4 v = *(const float4*)&su.stage[row][cc4];
        size_t idx = (size_t)rg * NPIX + n0 + cc4;
        float4 xv = *(const float4*)&xb[idx];
        v.x += bb + xv.x; v.y += bb + xv.y; v.z += bb + xv.z; v.w += bb + xv.w;
        *(float4*)&ob[idx] = v;
    }
}

// ---------------------------------------------------------------------------
extern "C" void kernel_launch(void* const* d_in, const int* in_sizes, int n_in,
                              void* d_out, int out_size)
{
    (void)in_sizes; (void)n_in; (void)out_size;
    const float* x     = (const float*)d_in[0];
    const float* Wq    = (const float*)d_in[1];
    const float* bq    = (const float*)d_in[2];
    const float* Wk    = (const float*)d_in[3];
    const float* bk    = (const float*)d_in[4];
    const float* Wv    = (const float*)d_in[5];
    const float* bv    = (const float*)d_in[6];
    const float* Wo    = (const float*)d_in[7];
    const float* bo    = (const float*)d_in[8];
    const float* gamma = (const float*)d_in[9];
    float* out = (float*)d_out;

    dim3 g1(NPIX / 64, B_);
    qkv_mma_kernel<<<g1, 256>>>(x, Wq, bq, Wk, bk, Wv, bv);

    dim3 g2(NSPLIT, B_);
    s_kernel<<<g2, 256>>>();

    softmax_kernel<<<B_, 512>>>();

    dim3 g3(CIN / 16, B_);
    w2_kernel<<<g3, 256>>>(Wo, gamma);

    dim3 g4(CIN / 64, NPIX / 128, B_);   // m fastest -> V slice L2 reuse
    out_mma_kernel<<<g4, 256>>>(x, bo, gamma, out);
}

// round 17
// speedup vs baseline: 1.0644x; 1.0644x over previous
#include <cuda_runtime.h>
#include <cuda_fp16.h>

#define B_    16
#define CIN   512
#define NPIX  4096
#define CC    64
#define NSPLIT 32

// Scratch (static device globals; no allocation)
__device__ float g_qkv[(size_t)B_ * 3 * CC * NPIX];          // [b][{q,k,v}][64][4096]
__device__ float g_Spart[(size_t)B_ * NSPLIT * CC * CC];     // split-K partials of S
__device__ float g_attn[(size_t)B_ * CC * CC];               // softmax(S) per batch
__device__ float g_W2[(size_t)B_ * CIN * CC];                // gamma * (Wo @ attn) per batch
// QKV weights prepacked in mma.sync A-fragment layout:
// [kt 0..31][rb16 0..11][lane 0..31][j 0..3]  (hi and lo fp16 pairs)
__device__ unsigned g_WfragH[32 * 12 * 32 * 4];
__device__ unsigned g_WfragL[32 * 12 * 32 * 4];

// ---------------------------------------------------------------------------
// fp16 3-term split helpers (a = hi + lo, both fp16; products accum in fp32)
// ---------------------------------------------------------------------------
__device__ __forceinline__ void split2(float x, float y, unsigned& hu, unsigned& lu) {
    __half hx = __float2half_rn(x), hy = __float2half_rn(y);
    __half2 H = __halves2half2(hx, hy);
    __half2 L = __floats2half2_rn(x - __half2float(hx), y - __half2float(hy));
    hu = reinterpret_cast<unsigned&>(H);
    lu = reinterpret_cast<unsigned&>(L);
}

__device__ __forceinline__ unsigned cvt_hi2(float x, float y) {
    __half2 H = __floats2half2_rn(x, y);
    return reinterpret_cast<unsigned&>(H);
}

__device__ __forceinline__ void mma_f16(float* d, const unsigned* a, const unsigned* b) {
    asm volatile(
        "mma.sync.aligned.m16n8k16.row.col.f32.f16.f16.f32 "
        "{%0,%1,%2,%3}, {%4,%5,%6,%7}, {%8,%9}, {%0,%1,%2,%3};"
        : "+f"(d[0]), "+f"(d[1]), "+f"(d[2]), "+f"(d[3])
        : "r"(a[0]), "r"(a[1]), "r"(a[2]), "r"(a[3]), "r"(b[0]), "r"(b[1]));
}

__device__ __forceinline__ void ldsm_x4(unsigned* r, unsigned addr) {
    asm volatile("ldmatrix.sync.aligned.m8n8.x4.shared.b16 {%0,%1,%2,%3}, [%4];"
                 : "=r"(r[0]), "=r"(r[1]), "=r"(r[2]), "=r"(r[3]) : "r"(addr));
}

__device__ __forceinline__ unsigned sptr(const void* p) {
    return (unsigned)__cvta_generic_to_shared(p);
}

#define PA  12   // A row stride in words (out_mma kernel only)
#define PBQ 72   // B row stride, N=64 tile
#define PBO 136  // B row stride, N=128 tile

// ---------------------------------------------------------------------------
// Kernel 0: pack QKV weights into fragment layout.
// Fragment word j of lane l for tile (kt, rb16):
//   row = rb16*16 + (l>>2) + (j&1)*8
//   k   = kt*16 + 2*(l&3) + (j>>1)*8   (half2 of k, k+1)
// rows 0-63 = Wq, 64-127 = Wk, 128-191 = Wv.
// grid 192 x 256 = 49152 threads, one output word pair each.
// ---------------------------------------------------------------------------
__global__ __launch_bounds__(256) void pack_wfrag_kernel(
    const float* __restrict__ Wq, const float* __restrict__ Wk,
    const float* __restrict__ Wv)
{
    int idx = blockIdx.x * 256 + threadIdx.x;   // 0..49151
    int j    = idx & 3;
    int lane = (idx >> 2) & 31;
    int rem  = idx >> 7;
    int rb16 = rem % 12;
    int kt   = rem / 12;

    int grow = rb16 * 16 + (lane >> 2) + (j & 1) * 8;
    int kb   = kt * 16 + 2 * (lane & 3) + (j >> 1) * 8;

    const float* W = (grow < 64) ? Wq : (grow < 128) ? Wk : Wv;
    int r = grow & 63;
    float w0 = W[(size_t)r * CIN + kb];
    float w1 = W[(size_t)r * CIN + kb + 1];
    unsigned h, l;
    split2(w0, w1, h, l);
    g_WfragH[idx] = h;
    g_WfragL[idx] = l;
}

// ---------------------------------------------------------------------------
// Kernel 1: FUSED QKV projection. A-fragments loaded straight from prepacked
// gmem (no smem staging, no ldsm, no weight conversion in the loop).
// M=192, N-tile=64, K=512. SMSP-balanced: warp wm handles tiles rb16 =
// {wm (Q), 4+wm (K), 8+wm (V)}; V 2-term, Q/K 3-term.
// grid (64 n-tiles, 16 batches), 256 threads (8 warps: 4 m x 2 n)
// ---------------------------------------------------------------------------
union SmemQKV {
    struct {
        unsigned Bh[2][8][PBQ], Bl[2][8][PBQ];   // 9216 B
    } ab;
    float stage[96][68];        // 26112 B (two-pass epilogue staging)
};

__global__ __launch_bounds__(256, 2) void qkv_mma_kernel(
    const float* __restrict__ x,
    const float* __restrict__ bq, const float* __restrict__ bk,
    const float* __restrict__ bv)
{
    const int n0 = blockIdx.x * 64;
    const int b  = blockIdx.y;
    const float* xb = x + (size_t)b * CIN * NPIX;
    float* out = g_qkv + (size_t)b * 3 * CC * NPIX;

    __shared__ SmemQKV su;

    const int tid  = threadIdx.x;
    const int warp = tid >> 5;
    const int lane = tid & 31;
    const int wm = warp & 3;          // 0..3
    const int wn = warp >> 2;         // 0..1
    const int g  = lane >> 2;
    const int t  = lane & 3;

    // B staging coords
    const bool bact = (tid < 128);
    const int jb   = tid >> 4;           // 0..7 for tid<128
    const int c4   = (tid & 15) * 4;     // 0..60

    float acc[3][4][4];
    #pragma unroll
    for (int mt = 0; mt < 3; mt++)
        #pragma unroll
        for (int nt = 0; nt < 4; nt++)
            #pragma unroll
            for (int i = 0; i < 4; i++) acc[mt][nt][i] = 0.f;

    const int NT = CIN / 16;  // 32
    float4 bP0, bP1;

    if (bact) {
        bP0 = *(const float4*)&xb[(size_t)(2 * jb) * NPIX + n0 + c4];
        bP1 = *(const float4*)&xb[(size_t)(2 * jb + 1) * NPIX + n0 + c4];
    }

    for (int it = 0; it < NT; it++) {
        const int s = it & 1;
        if (bact) {
            unsigned bh4[4], bl4[4];
            split2(bP0.x, bP1.x, bh4[0], bl4[0]);
            split2(bP0.y, bP1.y, bh4[1], bl4[1]);
            split2(bP0.z, bP1.z, bh4[2], bl4[2]);
            split2(bP0.w, bP1.w, bh4[3], bl4[3]);
            *(uint4*)&su.ab.Bh[s][jb][c4] = make_uint4(bh4[0], bh4[1], bh4[2], bh4[3]);
            *(uint4*)&su.ab.Bl[s][jb][c4] = make_uint4(bl4[0], bl4[1], bl4[2], bl4[3]);
        }
        __syncthreads();

        // A fragments straight from prepacked gmem (L1/L2 resident)
        unsigned ah[3][4], al[3][4];
        #pragma unroll
        for (int mt = 0; mt < 3; mt++) {
            size_t off = (((size_t)it * 12) + (mt * 4 + wm)) * 128 + lane * 4;
            *(uint4*)ah[mt] = *(const uint4*)&g_WfragH[off];
            *(uint4*)al[mt] = *(const uint4*)&g_WfragL[off];
        }

        if (it + 1 < NT && bact) {
            const int kk = (it + 1) * 16;
            bP0 = *(const float4*)&xb[(size_t)(kk + 2 * jb) * NPIX + n0 + c4];
            bP1 = *(const float4*)&xb[(size_t)(kk + 2 * jb + 1) * NPIX + n0 + c4];
        }

        unsigned bh[4][2], bl[4][2];
        #pragma unroll
        for (int nt = 0; nt < 4; nt++) {
            int nb = wn * 32 + nt * 8;
            bh[nt][0] = su.ab.Bh[s][t    ][nb + g];
            bh[nt][1] = su.ab.Bh[s][t + 4][nb + g];
            bl[nt][0] = su.ab.Bl[s][t    ][nb + g];
            bl[nt][1] = su.ab.Bl[s][t + 4][nb + g];
        }
        #pragma unroll
        for (int mt = 0; mt < 3; mt++) {
            #pragma unroll
            for (int nt = 0; nt < 4; nt++) {
                mma_f16(acc[mt][nt], al[mt], bh[nt]);
                if (mt != 2) mma_f16(acc[mt][nt], ah[mt], bl[nt]);   // V (mt==2): 2-term
                mma_f16(acc[mt][nt], ah[mt], bh[nt]);
            }
        }
        // no trailing barrier (B double-buffered)
    }
    __syncthreads();   // protect union reuse (stage aliases ab)

    // two-pass staged epilogue: rows [0,96) then [96,192)
    // warp tile mt covers global rows [mt*64 + wm*16, +16)
    #pragma unroll
    for (int pass = 0; pass < 2; pass++) {
        #pragma unroll
        for (int mt = 0; mt < 3; mt++) {
            int grow0 = mt * 64 + wm * 16;
            if (grow0 >= pass * 96 && grow0 < pass * 96 + 96) {
                int r0 = grow0 - pass * 96 + g;
                #pragma unroll
                for (int nt = 0; nt < 4; nt++) {
                    int c = wn * 32 + nt * 8 + 2 * t;
                    su.stage[r0][c]         = acc[mt][nt][0];
                    su.stage[r0][c + 1]     = acc[mt][nt][1];
                    su.stage[r0 + 8][c]     = acc[mt][nt][2];
                    su.stage[r0 + 8][c + 1] = acc[mt][nt][3];
                }
            }
        }
        __syncthreads();
        #pragma unroll
        for (int i = 0; i < 6; i++) {
            int e   = tid + i * 256;
            int row = e >> 4;
            int cc4 = (e & 15) * 4;
            int grow = pass * 96 + row;
            int jj  = grow >> 6;
            const float* bp = (jj == 0) ? bq : (jj == 1) ? bk : bv;
            float bb = bp[grow & 63];
            float4 v = *(const float4*)&su.stage[row][cc4];
            v.x += bb; v.y += bb; v.z += bb; v.w += bb;
            *(float4*)&out[(size_t)grow * NPIX + n0 + cc4] = v;
        }
        __syncthreads();
    }
}

// ---------------------------------------------------------------------------
// Kernel 2: split-K partials of S[b] = Q[64,4096] @ K_view[4096,64]  (fp32)
// ---------------------------------------------------------------------------
__global__ __launch_bounds__(256) void s_kernel()
{
    const int s = blockIdx.x;
    const int b = blockIdx.y;
    const float* Q  = g_qkv + (size_t)(b * 3 + 0) * CC * NPIX;
    const float* Kp = g_qkv + (size_t)(b * 3 + 1) * CC * NPIX;  // flat reshape view

    __shared__ float Qs[64][17];
    __shared__ float Ks[16][64];

    const int tid = threadIdx.x;
    const int tx = tid & 15, ty = tid >> 4;
    const int nbase = s * (NPIX / NSPLIT);   // 128 n per split

    float acc[4][4];
    #pragma unroll
    for (int i = 0; i < 4; i++)
        #pragma unroll
        for (int jj = 0; jj < 4; jj++) acc[i][jj] = 0.f;

    for (int kk = 0; kk < NPIX / NSPLIT; kk += 16) {
        #pragma unroll
        for (int e = tid; e < 1024; e += 256) {
            int i = e >> 4, k = e & 15;
            Qs[i][k] = Q[(size_t)i * NPIX + nbase + kk + k];
        }
        #pragma unroll
        for (int e = tid; e < 1024; e += 256) {
            int k = e >> 6, d = e & 63;
            Ks[k][d] = Kp[(size_t)(nbase + kk + k) * CC + d];
        }
        __syncthreads();
        #pragma unroll
        for (int k = 0; k < 16; k++) {
            float av[4];
            #pragma unroll
            for (int i = 0; i < 4; i++) av[i] = Qs[ty * 4 + i][k];
            float4 bv4 = *(const float4*)&Ks[k][tx * 4];
            float bv_[4] = {bv4.x, bv4.y, bv4.z, bv4.w};
            #pragma unroll
            for (int i = 0; i < 4; i++)
                #pragma unroll
                for (int jj = 0; jj < 4; jj++) acc[i][jj] += av[i] * bv_[jj];
        }
        __syncthreads();
    }
    float* part = g_Spart + ((size_t)b * NSPLIT + s) * CC * CC;
    #pragma unroll
    for (int i = 0; i < 4; i++)
        #pragma unroll
        for (int jj = 0; jj < 4; jj++)
            part[(ty * 4 + i) * CC + tx * 4 + jj] = acc[i][jj];
}

// ---------------------------------------------------------------------------
// Kernel 3a: reduce partials -> S, row softmax -> attn (global).
// ---------------------------------------------------------------------------
__global__ __launch_bounds__(512) void softmax_kernel()
{
    const int b = blockIdx.x;
    const int tid = threadIdx.x;
    __shared__ float sA[CC * CC];

    for (int e = tid; e < CC * CC; e += 512) {
        const float* p = g_Spart + (size_t)b * NSPLIT * CC * CC + e;
        float v = 0.f;
        #pragma unroll
        for (int s = 0; s < NSPLIT; s++) v += p[(size_t)s * CC * CC];
        sA[e] = v;
    }
    __syncthreads();

    if (tid < CC) {
        float* row = &sA[tid * CC];
        float mx = row[0];
        #pragma unroll
        for (int d = 1; d < CC; d++) mx = fmaxf(mx, row[d]);
        float sum = 0.f;
        #pragma unroll
        for (int d = 0; d < CC; d++) { float e = __expf(row[d] - mx); row[d] = e; sum += e; }
        float inv = 1.f / sum;
        #pragma unroll
        for (int d = 0; d < CC; d++) row[d] *= inv;
    }
    __syncthreads();

    float* ab = g_attn + (size_t)b * CC * CC;
    for (int e = tid; e < CC * CC; e += 512)
        ab[e] = sA[e];
}

// ---------------------------------------------------------------------------
// Kernel 3b: W2[b] = gamma * Wo @ attn[b].  grid (32 m-tiles of 16, 16 b).
// ---------------------------------------------------------------------------
__global__ __launch_bounds__(256) void w2_kernel(
    const float* __restrict__ Wo, const float* __restrict__ gamma)
{
    const int m0 = blockIdx.x * 16;
    const int b  = blockIdx.y;
    const int tid = threadIdx.x;

    __shared__ float aW[CC][CC + 4];
    __shared__ float wo[16][CC + 4];

    #pragma unroll
    for (int i = 0; i < 4; i++) {
        int e = tid + i * 256;
        int r = e >> 4, c4 = (e & 15) * 4;
        float4 va = *(const float4*)&g_attn[(size_t)b * CC * CC + r * CC + c4];
        *(float4*)&aW[r][c4] = va;
    }
    {
        int r = tid >> 4, c4 = (tid & 15) * 4;
        float4 vw = *(const float4*)&Wo[(size_t)(m0 + r) * CC + c4];
        *(float4*)&wo[r][c4] = vw;
    }
    __syncthreads();

    const int ol = tid >> 4;
    const int cs = (tid & 15) * 4;

    float acc[4] = {0.f, 0.f, 0.f, 0.f};

    #pragma unroll
    for (int e = 0; e < CC; e++) {
        float w = wo[ol][e];
        float4 v = *(const float4*)&aW[e][cs];
        acc[0] += w * v.x;
        acc[1] += w * v.y;
        acc[2] += w * v.z;
        acc[3] += w * v.w;
    }

    const float g = gamma[0];
    float* w2 = g_W2 + ((size_t)b * CIN + m0 + ol) * CC + cs;
    float4 v = make_float4(g * acc[0], g * acc[1], g * acc[2], g * acc[3]);
    *(float4*)w2 = v;
}

// ---------------------------------------------------------------------------
// Kernel 4: out = W2[b][512,64] @ V[b][64,4096] + gamma*bo + x.
// 2-term fp16 MMA: W2 split hi/lo, V hi only.
// grid (32 n-tiles, 8 m-tiles, 16 batches), 256 threads (8 warps, 2x4)
// ---------------------------------------------------------------------------
union SmemOut {
    struct {
        unsigned Ah[2][64][PA], Al[2][64][PA];    // 12288 B
        unsigned Bh[2][8][PBO];                   //  8704 B
    } ab;                       // 20992 B
    float stage[64][132];       // 33792 B
};

__global__ __launch_bounds__(256, 3) void out_mma_kernel(
    const float* __restrict__ x, const float* __restrict__ bo,
    const float* __restrict__ gamma, float* __restrict__ out)
{
    const int n0 = blockIdx.x * 128;
    const int m0 = blockIdx.y * 64;
    const int b  = blockIdx.z;
    const float* W  = g_W2 + (size_t)b * CIN * CC;
    const float* V  = g_qkv + (size_t)(b * 3 + 2) * CC * NPIX;
    const float* xb = x + (size_t)b * CIN * NPIX;
    float* ob = out + (size_t)b * CIN * NPIX;

    __shared__ SmemOut su;

    const int tid  = threadIdx.x;
    const int warp = tid >> 5;
    const int lane = tid & 31;
    const int wm = warp & 1;
    const int wn = warp >> 1;
    const int g  = lane >> 2;
    const int t  = lane & 3;

    const int lrow = lane & 15;
    const int lwB  = (lane >> 4) * 16;

    const int m_st = tid >> 2;
    const int k4   = (tid & 3) * 4;
    const int jb   = tid >> 5;
    const int n4b  = (tid & 31) * 4;

    float acc[2][4][4];
    #pragma unroll
    for (int mt = 0; mt < 2; mt++)
        #pragma unroll
        for (int nt = 0; nt < 4; nt++)
            #pragma unroll
            for (int i = 0; i < 4; i++) acc[mt][nt][i] = 0.f;

    const int NT = CC / 16;  // 4
    float4 aP, bP0, bP1;

    aP  = *(const float4*)&W[(size_t)(m0 + m_st) * CC + k4];
    bP0 = *(const float4*)&V[(size_t)(2 * jb) * NPIX + n0 + n4b];
    bP1 = *(const float4*)&V[(size_t)(2 * jb + 1) * NPIX + n0 + n4b];

    #pragma unroll
    for (int it = 0; it < NT; it++) {
        const int s = it & 1;
        {
            unsigned h0, l0, h1, l1;
            split2(aP.x, aP.y, h0, l0);
            split2(aP.z, aP.w, h1, l1);
            *(uint2*)&su.ab.Ah[s][m_st][k4 >> 1] = make_uint2(h0, h1);
            *(uint2*)&su.ab.Al[s][m_st][k4 >> 1] = make_uint2(l0, l1);
            unsigned bh4[4];
            bh4[0] = cvt_hi2(bP0.x, bP1.x);
            bh4[1] = cvt_hi2(bP0.y, bP1.y);
            bh4[2] = cvt_hi2(bP0.z, bP1.z);
            bh4[3] = cvt_hi2(bP0.w, bP1.w);
            *(uint4*)&su.ab.Bh[s][jb][n4b] = make_uint4(bh4[0], bh4[1], bh4[2], bh4[3]);
        }
        __syncthreads();

        if (it + 1 < NT) {
            const int kk = (it + 1) * 16;
            aP  = *(const float4*)&W[(size_t)(m0 + m_st) * CC + kk + k4];
            bP0 = *(const float4*)&V[(size_t)(kk + 2 * jb) * NPIX + n0 + n4b];
            bP1 = *(const float4*)&V[(size_t)(kk + 2 * jb + 1) * NPIX + n0 + n4b];
        }

        unsigned ah[2][4], al[2][4], bh[4][2];
        const unsigned baseAh = sptr(&su.ab.Ah[s][0][0]);
        const unsigned baseAl = sptr(&su.ab.Al[s][0][0]);
        #pragma unroll
        for (int mt = 0; mt < 2; mt++) {
            int rb = wm * 32 + mt * 16;
            unsigned roff = (unsigned)(rb + lrow) * (PA * 4) + lwB;
            ldsm_x4(ah[mt], baseAh + roff);
            ldsm_x4(al[mt], baseAl + roff);
        }
        #pragma unroll
        for (int nt = 0; nt < 4; nt++) {
            int nb = wn * 32 + nt * 8;
            bh[nt][0] = su.ab.Bh[s][t    ][nb + g];
            bh[nt][1] = su.ab.Bh[s][t + 4][nb + g];
        }
        #pragma unroll
        for (int mt = 0; mt < 2; mt++)
            #pragma unroll
            for (int nt = 0; nt < 4; nt++)
                mma_f16(acc[mt][nt], al[mt], bh[nt]);
        #pragma unroll
        for (int mt = 0; mt < 2; mt++)
            #pragma unroll
            for (int nt = 0; nt < 4; nt++)
                mma_f16(acc[mt][nt], ah[mt], bh[nt]);
        // no trailing barrier (double-buffered)
    }
    __syncthreads();   // protect union reuse

    // stage accumulators into smem
    #pragma unroll
    for (int mt = 0; mt < 2; mt++) {
        int r0 = wm * 32 + mt * 16 + g;
        #pragma unroll
        for (int nt = 0; nt < 4; nt++) {
            int c = wn * 32 + nt * 8 + 2 * t;
            su.stage[r0][c]         = acc[mt][nt][0];
            su.stage[r0][c + 1]     = acc[mt][nt][1];
            su.stage[r0 + 8][c]     = acc[mt][nt][2];
            su.stage[r0 + 8][c + 1] = acc[mt][nt][3];
        }
    }
    __syncthreads();

    // coalesced stream: out = stage + gamma*bo + x   (64x128 = 2048 float4)
    const float gm = gamma[0];
    #pragma unroll
    for (int i = 0; i < 8; i++) {
        int e   = tid + i * 256;
        int row = e >> 5;
        int cc4 = (e & 31) * 4;
        int rg  = m0 + row;
        float bb = gm * bo[rg];
        float4 v = *(const float4*)&su.stage[row][cc4];
        size_t idx = (size_t)rg * NPIX + n0 + cc4;
        float4 xv = *(const float4*)&xb[idx];
        v.x += bb + xv.x; v.y += bb + xv.y; v.z += bb + xv.z; v.w += bb + xv.w;
        *(float4*)&ob[idx] = v;
    }
}

// ---------------------------------------------------------------------------
extern "C" void kernel_launch(void* const* d_in, const int* in_sizes, int n_in,
                              void* d_out, int out_size)
{
    (void)in_sizes; (void)n_in; (void)out_size;
    const float* x     = (const float*)d_in[0];
    const float* Wq    = (const float*)d_in[1];
    const float* bq    = (const float*)d_in[2];
    const float* Wk    = (const float*)d_in[3];
    const float* bk    = (const float*)d_in[4];
    const float* Wv    = (const float*)d_in[5];
    const float* bv    = (const float*)d_in[6];
    const float* Wo    = (const float*)d_in[7];
    const float* bo    = (const float*)d_in[8];
    const float* gamma = (const float*)d_in[9];
    float* out = (float*)d_out;

    pack_wfrag_kernel<<<192, 256>>>(Wq, Wk, Wv);

    dim3 g1(NPIX / 64, B_);
    qkv_mma_kernel<<<g1, 256>>>(x, bq, bk, bv);

    dim3 g2(NSPLIT, B_);
    s_kernel<<<g2, 256>>>();

    softmax_kernel<<<B_, 512>>>();

    dim3 g3(CIN / 16, B_);
    w2_kernel<<<g3, 256>>>(Wo, gamma);

    dim3 g4(NPIX / 128, CIN / 64, B_);
    out_mma_kernel<<<g4, 256>>>(x, bo, gamma, out);
}